// round 15
// baseline (speedup 1.0000x reference)
#include <cuda_runtime.h>
#include <cuda_bf16.h>
#include <cstdint>

#define BB 2
#define SS 1024
#define DMOD 1024
#define HH 16
#define DH 64
#define NR 21     // 2*MAX_REL+1
#define K2 2048   // 2-plane storage: [hi | lo] per row
// logical GEMM K = 3072 via region remap: A:(hi,lo,hi)  B:(hi,hi,lo)

// ============================================================================
// scratch (static device globals: no allocations allowed)
// ============================================================================
__device__ __nv_bfloat16 g_Qh[BB * SS * DMOD];
__device__ __nv_bfloat16 g_Ql[BB * SS * DMOD];
__device__ __nv_bfloat16 g_Kh[BB * SS * DMOD];
__device__ __nv_bfloat16 g_Kl[BB * SS * DMOD];
__device__ __nv_bfloat16 g_Vh[BB * SS * DMOD];
__device__ __nv_bfloat16 g_Vl[BB * SS * DMOD];

__device__ __nv_bfloat16 g_q2[BB * SS * K2];
__device__ __nv_bfloat16 g_k2[BB * SS * K2];
__device__ __nv_bfloat16 g_v2[BB * SS * K2];
__device__ __nv_bfloat16 g_x2[BB * SS * K2];
__device__ __nv_bfloat16 g_wq2[DMOD * K2];
__device__ __nv_bfloat16 g_wk2[DMOD * K2];
__device__ __nv_bfloat16 g_wv2[DMOD * K2];
__device__ __nv_bfloat16 g_w02[DMOD * K2];

// ============================================================================
// batched split kernel: fp32 -> bf16 [hi | lo]
// ============================================================================
struct SplitPack {
    const float* in[7];
    __nv_bfloat16* out[7];
    int n[7];
};

__global__ __launch_bounds__(256) void split_multi(SplitPack p) {
    const int sl = blockIdx.y;
    const int n = p.n[sl];
    int i = blockIdx.x * blockDim.x + threadIdx.x;
    if (i >= n) return;
    const float* in = p.in[sl];
    __nv_bfloat16* out = p.out[sl];
    int m = i >> 10;          // K = 1024
    int k = i & 1023;
    float x = in[i];
    __nv_bfloat16 h = __float2bfloat16_rn(x);
    float r = x - __bfloat162float(h);
    __nv_bfloat16 l = __float2bfloat16_rn(r);
    size_t base = (size_t)m * K2 + k;
    out[base] = h;
    out[base + 1024] = l;
}

// ============================================================================
// mma.sync / cp.async helpers
// ============================================================================
__device__ __forceinline__ uint32_t smem_u32(const void* p) {
    uint32_t a;
    asm("{ .reg .u64 t; cvta.to.shared.u64 t, %1; cvt.u32.u64 %0, t; }"
        : "=r"(a) : "l"(p));
    return a;
}

#define CP_ASYNC16(dst, src) \
    asm volatile("cp.async.cg.shared.global [%0], [%1], 16;" \
                 :: "r"(dst), "l"(src) : "memory")
#define CP_COMMIT() asm volatile("cp.async.commit_group;" ::: "memory")
#define CP_WAIT0()  asm volatile("cp.async.wait_group 0;" ::: "memory")

__device__ __forceinline__ void ldmx4(uint32_t& r0, uint32_t& r1,
                                      uint32_t& r2, uint32_t& r3,
                                      uint32_t addr) {
    asm volatile(
        "ldmatrix.sync.aligned.m8n8.x4.shared.b16 {%0,%1,%2,%3}, [%4];"
        : "=r"(r0), "=r"(r1), "=r"(r2), "=r"(r3) : "r"(addr));
}

__device__ __forceinline__ void ldmx4t(uint32_t& r0, uint32_t& r1,
                                       uint32_t& r2, uint32_t& r3,
                                       uint32_t addr) {
    asm volatile(
        "ldmatrix.sync.aligned.m8n8.x4.trans.shared.b16 {%0,%1,%2,%3}, [%4];"
        : "=r"(r0), "=r"(r1), "=r"(r2), "=r"(r3) : "r"(addr));
}

__device__ __forceinline__ void mma16816(float* c, const uint32_t* a,
                                         const uint32_t* b) {
    asm volatile(
        "mma.sync.aligned.m16n8k16.row.col.f32.bf16.bf16.f32 "
        "{%0,%1,%2,%3}, {%4,%5,%6,%7}, {%8,%9}, {%0,%1,%2,%3};"
        : "+f"(c[0]), "+f"(c[1]), "+f"(c[2]), "+f"(c[3])
        : "r"(a[0]), "r"(a[1]), "r"(a[2]), "r"(a[3]), "r"(b[0]), "r"(b[1]));
}

__device__ __forceinline__ void split2(float x, __nv_bfloat16& h, __nv_bfloat16& l) {
    h = __float2bfloat16_rn(x);
    l = __float2bfloat16_rn(x - __bfloat162float(h));
}

__device__ __forceinline__ uint32_t pack_bf2(__nv_bfloat16 a, __nv_bfloat16 b) {
    __nv_bfloat162 p = __halves2bfloat162(a, b);
    return *(uint32_t*)&p;
}

// ============================================================================
// bf16 HMMA GEMM, logical K=3072 over 2-plane storage, BK=64,
// cp.async single-sync pipeline, templated tile: 128xBN.
//   BN=128: 8 warps = 2M x 4N (MI=4)   -- projections
//   BN=64 : 8 warps = 4M x 2N (MI=2)   -- out-projection (2x grid width)
// mode 0: C fp32 = acc + bias;  mode 1: split bf16 hi/lo planes.
// ============================================================================
struct GemmArgs {
    const __nv_bfloat16* A[3];
    const __nv_bfloat16* B[3];
    const float* bias[3];
    float* C[3];
    __nv_bfloat16* Ch[3];
    __nv_bfloat16* Cl[3];
    int mode;
};

#define GRS 72                        // halves per smem row (144 B)
#define GBUFA (128 * GRS)             // A stage halves

template <int BN, int MI>
__global__ __launch_bounds__(256, 2) void gemm_mma(GemmArgs ga, int N) {
    extern __shared__ __align__(16) __nv_bfloat16 gsm[];
    constexpr int GBUFB = BN * GRS;
    __nv_bfloat16* As = gsm;                  // [2][GBUFA]
    __nv_bfloat16* Bs = gsm + 2 * GBUFA;      // [2][GBUFB]

    const int t = threadIdx.x;
    const int lane = t & 31;
    const int wid = t >> 5;
    const int wm = (BN == 128) ? (wid & 1) * 64 : (wid & 3) * 32;
    const int wn = (BN == 128) ? (wid >> 1) * 32 : (wid >> 2) * 32;
    const int grp = lane >> 2;
    const int tig = lane & 3;
    const int z = blockIdx.z;
    const int m0 = blockIdx.y * 128;
    const int n0 = blockIdx.x * BN;

    const __nv_bfloat16* Ag = ga.A[z];
    const __nv_bfloat16* Bg = ga.B[z];
    const float* bias = ga.bias[z];

    // A loader: 2 thr/row, 32 halves each (4 x 16B)
    const int arow = t >> 1;
    const int acol = (t & 1) * 32;
    const __nv_bfloat16* Ap = Ag + (size_t)(m0 + arow) * K2;
    const uint32_t sstA = arow * (GRS * 2) + acol * 2;
    // B loader: (256/BN) thr/row
    constexpr int TPRB = 256 / BN;
    constexpr int BH = 64 / TPRB;             // halves per thread
    constexpr int BCH = BH / 8;               // 16B chunks per thread
    const int brow = t / TPRB;
    const int bcol = (t % TPRB) * BH;
    const __nv_bfloat16* Bp = Bg + (size_t)(n0 + brow) * K2;
    const uint32_t sstB = brow * (GRS * 2) + bcol * 2;

    const uint32_t asb = smem_u32(As);
    const uint32_t bsb = smem_u32(Bs);

    const uint32_t a_base = asb + (wm + (lane & 15)) * (GRS * 2) + ((lane >> 4) * 8) * 2;
    const uint32_t b_base = bsb + (wn + (lane & 7) + ((lane >> 4) & 1) * 8) * (GRS * 2) +
                            (((lane >> 3) & 1) * 8) * 2;

    float acc[MI][4][4];
#pragma unroll
    for (int mi = 0; mi < MI; ++mi)
#pragma unroll
        for (int ni = 0; ni < 4; ++ni)
#pragma unroll
            for (int r = 0; r < 4; ++r) acc[mi][ni][r] = 0.f;

    // region remap: A regions (hi,lo,hi) -> {0,1024,0}; B (hi,hi,lo) -> {0,0,1024}
    auto a_src = [&](int kt) {
        const int reg = kt >> 4;
        return Ap + (reg == 1 ? 1024 : 0) + (kt & 15) * 64 + acol;
    };
    auto b_src = [&](int kt) {
        const int reg = kt >> 4;
        return Bp + (reg == 2 ? 1024 : 0) + (kt & 15) * 64 + bcol;
    };

    {
        const __nv_bfloat16* a0 = a_src(0);
        const __nv_bfloat16* b0 = b_src(0);
#pragma unroll
        for (int c = 0; c < 4; ++c) CP_ASYNC16(asb + sstA + c * 16, a0 + c * 8);
#pragma unroll
        for (int c = 0; c < BCH; ++c) CP_ASYNC16(bsb + sstB + c * 16, b0 + c * 8);
        CP_COMMIT();
    }

    const int NT = 48;   // 3072 / 64
    for (int kt = 0; kt < NT; ++kt) {
        const int buf = kt & 1;
        CP_WAIT0();
        __syncthreads();

        if (kt + 1 < NT) {
            const uint32_t nbA = (buf ^ 1) * (GBUFA * 2);
            const uint32_t nbB = (buf ^ 1) * (GBUFB * 2);
            const __nv_bfloat16* an = a_src(kt + 1);
            const __nv_bfloat16* bn = b_src(kt + 1);
#pragma unroll
            for (int c = 0; c < 4; ++c) CP_ASYNC16(asb + nbA + sstA + c * 16, an + c * 8);
#pragma unroll
            for (int c = 0; c < BCH; ++c) CP_ASYNC16(bsb + nbB + sstB + c * 16, bn + c * 8);
            CP_COMMIT();
        }

        const uint32_t abuf = a_base + buf * (GBUFA * 2);
        const uint32_t bbuf = b_base + buf * (GBUFB * 2);
#pragma unroll
        for (int ks = 0; ks < 4; ++ks) {
            uint32_t a[MI][4], b[4][2];
#pragma unroll
            for (int mi = 0; mi < MI; ++mi)
                ldmx4(a[mi][0], a[mi][1], a[mi][2], a[mi][3],
                      abuf + mi * 16 * (GRS * 2) + ks * 32);
#pragma unroll
            for (int nb2 = 0; nb2 < 2; ++nb2)
                ldmx4(b[nb2 * 2][0], b[nb2 * 2][1], b[nb2 * 2 + 1][0],
                      b[nb2 * 2 + 1][1],
                      bbuf + nb2 * 16 * (GRS * 2) + ks * 32);
#pragma unroll
            for (int mi = 0; mi < MI; ++mi)
#pragma unroll
                for (int ni = 0; ni < 4; ++ni)
                    mma16816(acc[mi][ni], a[mi], b[ni]);
        }
    }

    if (ga.mode == 0) {
        float* C = ga.C[z];
#pragma unroll
        for (int ni = 0; ni < 4; ++ni) {
            const int col = n0 + wn + ni * 8 + tig * 2;
            const float2 bv = *(const float2*)&bias[col];
#pragma unroll
            for (int mi = 0; mi < MI; ++mi) {
                const int row = m0 + wm + mi * 16 + grp;
                *(float2*)&C[(size_t)row * N + col] =
                    make_float2(acc[mi][ni][0] + bv.x, acc[mi][ni][1] + bv.y);
                *(float2*)&C[(size_t)(row + 8) * N + col] =
                    make_float2(acc[mi][ni][2] + bv.x, acc[mi][ni][3] + bv.y);
            }
        }
    } else {
        __nv_bfloat16* Ch = ga.Ch[z];
        __nv_bfloat16* Cl = ga.Cl[z];
#pragma unroll
        for (int ni = 0; ni < 4; ++ni) {
            const int col = n0 + wn + ni * 8 + tig * 2;
            const float2 bv = *(const float2*)&bias[col];
#pragma unroll
            for (int mi = 0; mi < MI; ++mi) {
                const int row = m0 + wm + mi * 16 + grp;
                float f00 = acc[mi][ni][0] + bv.x, f01 = acc[mi][ni][1] + bv.y;
                float f10 = acc[mi][ni][2] + bv.x, f11 = acc[mi][ni][3] + bv.y;
                __nv_bfloat16 h00, l00, h01, l01, h10, l10, h11, l11;
                split2(f00, h00, l00);
                split2(f01, h01, l01);
                split2(f10, h10, l10);
                split2(f11, h11, l11);
                const size_t i0 = (size_t)row * N + col;
                const size_t i1 = (size_t)(row + 8) * N + col;
                *(__nv_bfloat162*)(Ch + i0) = __halves2bfloat162(h00, h01);
                *(__nv_bfloat162*)(Cl + i0) = __halves2bfloat162(l00, l01);
                *(__nv_bfloat162*)(Ch + i1) = __halves2bfloat162(h10, h11);
                *(__nv_bfloat162*)(Cl + i1) = __halves2bfloat162(l10, l11);
            }
        }
    }
}

// ============================================================================
// Tensor-core fused attention v5 (FA2 register-S + clip-band fast path).
// Epilogue writes x2 in 2-plane [hi | lo] layout. Unchanged from R14.
// ============================================================================
#define QRS 72
#define ATT_SMEM 105984
#define S32 0.03125f

__global__ __launch_bounds__(256, 2) void attn_mma(
    const __nv_bfloat16* __restrict__ Qhg, const __nv_bfloat16* __restrict__ Qlg,
    const __nv_bfloat16* __restrict__ Khg, const __nv_bfloat16* __restrict__ Klg,
    const __nv_bfloat16* __restrict__ Vhg, const __nv_bfloat16* __restrict__ Vlg,
    const float* __restrict__ rkt, const float* __restrict__ rvt,
    __nv_bfloat16* __restrict__ x2) {
    extern __shared__ char smc[];
    __nv_bfloat16* Qh = (__nv_bfloat16*)(smc);
    __nv_bfloat16* Ql = (__nv_bfloat16*)(smc + 18432);
    __nv_bfloat16* Kh = (__nv_bfloat16*)(smc + 36864);
    __nv_bfloat16* Kl = (__nv_bfloat16*)(smc + 46080);
    __nv_bfloat16* Vh = (__nv_bfloat16*)(smc + 55296);
    __nv_bfloat16* Vl = (__nv_bfloat16*)(smc + 64512);
    float* rk = (float*)(smc + 73728);
    float* rv = (float*)(smc + 79104);
    float* pp = (float*)(smc + 84480);
    float* cs = (float*)(smc + 95232);

    const uint32_t sQh = smem_u32(Qh), sQl = smem_u32(Ql);
    const uint32_t sKh = smem_u32(Kh), sKl = smem_u32(Kl);
    const uint32_t sVh = smem_u32(Vh), sVl = smem_u32(Vl);

    const int t = threadIdx.x;
    const int lane = t & 31;
    const int w = t >> 5;
    const int grp = lane >> 2;
    const int tig = lane & 3;
    const int q0 = blockIdx.x * 128;
    const int h = blockIdx.y;
    const int b = blockIdx.z;
    const size_t hoff = (size_t)h * DH;
    const size_t gbase = (size_t)b * SS * DMOD + hoff;

    const int ch = t & 7;
    const int r32 = t >> 3;

    {
        const __nv_bfloat16* qg[2] = {Qhg + gbase, Qlg + gbase};
        __nv_bfloat16* qs[2] = {Qh, Ql};
#pragma unroll
        for (int i = 0; i < 8; ++i) {
            const int pl = i >> 2;
            const int row = r32 + (i & 3) * 32;
            *(uint4*)(qs[pl] + row * QRS + ch * 8) =
                *(const uint4*)(qg[pl] + (size_t)(q0 + row) * DMOD + ch * 8);
        }
    }
    for (int i = t; i < NR * 64; i += 256) { rk[i] = rkt[i]; rv[i] = rvt[i]; }
    for (int i = t; i < 128 * NR; i += 256) cs[i] = 0.f;
    __syncthreads();

    for (int e = t; e < 128 * NR; e += 256) {
        int qq = e / NR, j = e - qq * NR;
        float s = 0.f;
#pragma unroll 16
        for (int d = 0; d < 64; ++d)
            s += (__bfloat162float(Qh[qq * QRS + d]) +
                  __bfloat162float(Ql[qq * QRS + d])) * rk[j * 64 + d];
        pp[e] = s;
    }

    float o[8][4];
#pragma unroll
    for (int ni = 0; ni < 8; ++ni)
#pragma unroll
        for (int r = 0; r < 4; ++r) o[ni][r] = 0.f;

    float l0a[2] = {0.f, 0.f};
    float l20a[2] = {0.f, 0.f};

    const uint32_t a_off = (w * 16 + (lane & 15)) * (QRS * 2) + ((lane >> 4) * 8) * 2;
    const uint32_t b_off = ((lane & 7) + ((lane >> 4) & 1) * 8) * (QRS * 2) +
                           (((lane >> 3) & 1) * 8) * 2;
    const uint32_t vb_row = (lane & 7) + ((lane >> 3) & 1) * 8;
    const uint32_t vb_cb  = ((lane >> 4) * 8) * 2;

    const __nv_bfloat16* kvg[4] = {Khg + gbase, Klg + gbase, Vhg + gbase, Vlg + gbase};
    __nv_bfloat16* kvs[4] = {Kh, Kl, Vh, Vl};

    for (int kt = 0; kt < 16; ++kt) {
        const int k0 = kt * 64;
        __syncthreads();

#pragma unroll
        for (int i = 0; i < 8; ++i) {
            const int pl = i >> 1;
            const int row = r32 + (i & 1) * 32;
            *(uint4*)(kvs[pl] + row * QRS + ch * 8) =
                *(const uint4*)(kvg[pl] + (size_t)(k0 + row) * DMOD + ch * 8);
        }
        __syncthreads();

        float s[8][4];
#pragma unroll
        for (int ni = 0; ni < 8; ++ni)
#pragma unroll
            for (int r = 0; r < 4; ++r) s[ni][r] = 0.f;

#pragma unroll
        for (int ks = 0; ks < 4; ++ks) {
            uint32_t ah[4], al[4];
            ldmx4(ah[0], ah[1], ah[2], ah[3], sQh + a_off + ks * 32);
            ldmx4(al[0], al[1], al[2], al[3], sQl + a_off + ks * 32);
#pragma unroll
            for (int nb = 0; nb < 4; ++nb) {
                uint32_t kh[4], kl[4];
                ldmx4(kh[0], kh[1], kh[2], kh[3],
                      sKh + b_off + nb * 16 * (QRS * 2) + ks * 32);
                ldmx4(kl[0], kl[1], kl[2], kl[3],
                      sKl + b_off + nb * 16 * (QRS * 2) + ks * 32);
                uint32_t bh0[2] = {kh[0], kh[1]}, bh1[2] = {kh[2], kh[3]};
                uint32_t bl0[2] = {kl[0], kl[1]}, bl1[2] = {kl[2], kl[3]};
                mma16816(s[nb * 2],     ah, bh0);
                mma16816(s[nb * 2],     al, bh0);
                mma16816(s[nb * 2],     ah, bl0);
                mma16816(s[nb * 2 + 1], ah, bh1);
                mma16816(s[nb * 2 + 1], al, bh1);
                mma16816(s[nb * 2 + 1], ah, bl1);
            }
        }

        uint32_t ahf[4][4], alf[4][4];
        const int wq0 = q0 + w * 16;
        const int dmax = k0 + 63 - wq0;
        const int dmin = k0 - (wq0 + 15);

        if (dmax <= -10 || dmin >= 10) {
            const int cls = (dmax <= -10) ? 0 : 20;
            float* lacc = (dmax <= -10) ? l0a : l20a;
#pragma unroll
            for (int hf = 0; hf < 2; ++hf) {
                const int row = w * 16 + grp + hf * 8;
                const float ppc = pp[row * NR + cls];
                float acc = 0.f;
#pragma unroll
                for (int ni = 0; ni < 8; ++ni) {
                    const float f0 = (s[ni][hf * 2 + 0] + ppc) * S32;
                    const float f1 = (s[ni][hf * 2 + 1] + ppc) * S32;
                    acc += f0;
                    acc += f1;
                    __nv_bfloat16 h0, lo0, h1, lo1;
                    split2(f0, h0, lo0);
                    split2(f1, h1, lo1);
                    const int kc = ni >> 1;
                    const int sub = (ni & 1) * 2 + hf;
                    ahf[kc][sub] = pack_bf2(h0, h1);
                    alf[kc][sub] = pack_bf2(lo0, lo1);
                }
                lacc[hf] += acc;
            }
        } else {
#pragma unroll
            for (int ni = 0; ni < 8; ++ni) {
                const int colg = k0 + ni * 8 + tig * 2;
#pragma unroll
                for (int hf = 0; hf < 2; ++hf) {
                    const int row = w * 16 + grp + hf * 8;
                    const int gq = q0 + row;
                    const float* ppr = pp + row * NR;
                    const int d0 = colg - gq;
                    const int d1 = d0 + 1;
                    const int c0 = d0 < -10 ? 0 : (d0 > 10 ? 20 : d0 + 10);
                    const int c1 = d1 < -10 ? 0 : (d1 > 10 ? 20 : d1 + 10);
                    const float f0 = (s[ni][hf * 2 + 0] + ppr[c0]) * S32;
                    const float f1 = (s[ni][hf * 2 + 1] + ppr[c1]) * S32;
                    if (d0 <= -10)      l0a[hf]  += f0;
                    else if (d0 >= 10)  l20a[hf] += f0;
                    else                cs[row * NR + d0 + 10] += f0;
                    if (d1 <= -10)      l0a[hf]  += f1;
                    else if (d1 >= 10)  l20a[hf] += f1;
                    else                cs[row * NR + d1 + 10] += f1;
                    __nv_bfloat16 h0, lo0, h1, lo1;
                    split2(f0, h0, lo0);
                    split2(f1, h1, lo1);
                    const int kc = ni >> 1;
                    const int sub = (ni & 1) * 2 + hf;
                    ahf[kc][sub] = pack_bf2(h0, h1);
                    alf[kc][sub] = pack_bf2(lo0, lo1);
                }
            }
        }

#pragma unroll
        for (int kc = 0; kc < 4; ++kc) {
#pragma unroll
            for (int nb = 0; nb < 4; ++nb) {
                uint32_t vh[4], vl[4];
                ldmx4t(vh[0], vh[1], vh[2], vh[3],
                       sVh + (kc * 16 + vb_row) * (QRS * 2) + vb_cb + nb * 32);
                ldmx4t(vl[0], vl[1], vl[2], vl[3],
                       sVl + (kc * 16 + vb_row) * (QRS * 2) + vb_cb + nb * 32);
                uint32_t bh0[2] = {vh[0], vh[1]}, bh1[2] = {vh[2], vh[3]};
                uint32_t bl0[2] = {vl[0], vl[1]}, bl1[2] = {vl[2], vl[3]};
                mma16816(o[nb * 2],     ahf[kc], bh0);
                mma16816(o[nb * 2],     alf[kc], bh0);
                mma16816(o[nb * 2],     ahf[kc], bl0);
                mma16816(o[nb * 2 + 1], ahf[kc], bh1);
                mma16816(o[nb * 2 + 1], alf[kc], bh1);
                mma16816(o[nb * 2 + 1], ahf[kc], bl1);
            }
        }
    }

#pragma unroll
    for (int hf = 0; hf < 2; ++hf) {
        float v0 = l0a[hf];
        v0 += __shfl_xor_sync(0xffffffffu, v0, 1);
        v0 += __shfl_xor_sync(0xffffffffu, v0, 2);
        float v20 = l20a[hf];
        v20 += __shfl_xor_sync(0xffffffffu, v20, 1);
        v20 += __shfl_xor_sync(0xffffffffu, v20, 2);
        if (tig == 0) {
            const int row = w * 16 + grp + hf * 8;
            cs[row * NR + 0]  += v0;
            cs[row * NR + 20] += v20;
        }
    }
    __syncwarp();

#pragma unroll
    for (int ni = 0; ni < 8; ++ni) {
#pragma unroll
        for (int hf = 0; hf < 2; ++hf) {
            const int row = w * 16 + grp + hf * 8;
            const int col = ni * 8 + tig * 2;
            float a0 = o[ni][hf * 2 + 0];
            float a1 = o[ni][hf * 2 + 1];
            const float* csr = cs + row * NR;
#pragma unroll
            for (int j = 0; j < NR; ++j) {
                const float c = csr[j];
                a0 += c * rv[j * 64 + col];
                a1 += c * rv[j * 64 + col + 1];
            }
            __nv_bfloat16 h0, l0b, h1, l1b;
            split2(a0, h0, l0b);
            split2(a1, h1, l1b);
            const size_t base = ((size_t)b * SS + q0 + row) * K2 + hoff + col;
            *(__nv_bfloat162*)(x2 + base)        = __halves2bfloat162(h0, h1);
            *(__nv_bfloat162*)(x2 + base + 1024) = __halves2bfloat162(l0b, l1b);
        }
    }
}

// ============================================================================
// launch
// ============================================================================
extern "C" void kernel_launch(void* const* d_in, const int* in_sizes, int n_in,
                              void* d_out, int out_size) {
    const float* q   = (const float*)d_in[0];
    const float* k   = (const float*)d_in[1];
    const float* v   = (const float*)d_in[2];
    const float* Wq  = (const float*)d_in[4];
    const float* bq  = (const float*)d_in[5];
    const float* Wk  = (const float*)d_in[6];
    const float* bk  = (const float*)d_in[7];
    const float* Wv  = (const float*)d_in[8];
    const float* bv  = (const float*)d_in[9];
    const float* W0  = (const float*)d_in[10];
    const float* b0  = (const float*)d_in[11];
    const float* rkt = (const float*)d_in[12];
    const float* rvt = (const float*)d_in[13];

    __nv_bfloat16 *Qh, *Ql, *Kh, *Kl, *Vh, *Vl;
    cudaGetSymbolAddress((void**)&Qh, g_Qh);
    cudaGetSymbolAddress((void**)&Ql, g_Ql);
    cudaGetSymbolAddress((void**)&Kh, g_Kh);
    cudaGetSymbolAddress((void**)&Kl, g_Kl);
    cudaGetSymbolAddress((void**)&Vh, g_Vh);
    cudaGetSymbolAddress((void**)&Vl, g_Vl);
    __nv_bfloat16 *q2, *k2, *v2, *x2, *wq2, *wk2, *wv2, *w02;
    cudaGetSymbolAddress((void**)&q2, g_q2);
    cudaGetSymbolAddress((void**)&k2, g_k2);
    cudaGetSymbolAddress((void**)&v2, g_v2);
    cudaGetSymbolAddress((void**)&x2, g_x2);
    cudaGetSymbolAddress((void**)&wq2, g_wq2);
    cudaGetSymbolAddress((void**)&wk2, g_wk2);
    cudaGetSymbolAddress((void**)&wv2, g_wv2);
    cudaGetSymbolAddress((void**)&w02, g_w02);

    const int M = BB * SS;          // 2048
    const int NACT = M * DMOD;      // 2M
    const int NW = DMOD * DMOD;     // 1M

    // one batched split launch for all 7 tensors
    SplitPack sp;
    sp.in[0] = q;  sp.out[0] = q2;  sp.n[0] = NACT;
    sp.in[1] = k;  sp.out[1] = k2;  sp.n[1] = NACT;
    sp.in[2] = v;  sp.out[2] = v2;  sp.n[2] = NACT;
    sp.in[3] = Wq; sp.out[3] = wq2; sp.n[3] = NW;
    sp.in[4] = Wk; sp.out[4] = wk2; sp.n[4] = NW;
    sp.in[5] = Wv; sp.out[5] = wv2; sp.n[5] = NW;
    sp.in[6] = W0; sp.out[6] = w02; sp.n[6] = NW;
    split_multi<<<dim3(NACT / 256, 7), 256>>>(sp);

    constexpr int GSMEM128 = 2 * (GBUFA + 128 * GRS) * 2;   // 73728
    constexpr int GSMEM64  = 2 * (GBUFA + 64 * GRS) * 2;    // 55296
    cudaFuncSetAttribute(gemm_mma<128, 4>,
                         cudaFuncAttributeMaxDynamicSharedMemorySize, GSMEM128);
    cudaFuncSetAttribute(gemm_mma<64, 2>,
                         cudaFuncAttributeMaxDynamicSharedMemorySize, GSMEM64);

    // fused q/k/v projections -> pre-split bf16 hi/lo planes (128x128 tiles)
    GemmArgs pa;
    pa.A[0] = q2;  pa.A[1] = k2;  pa.A[2] = v2;
    pa.B[0] = wq2; pa.B[1] = wk2; pa.B[2] = wv2;
    pa.bias[0] = bq; pa.bias[1] = bk; pa.bias[2] = bv;
    pa.C[0] = pa.C[1] = pa.C[2] = nullptr;
    pa.Ch[0] = Qh; pa.Ch[1] = Kh; pa.Ch[2] = Vh;
    pa.Cl[0] = Ql; pa.Cl[1] = Kl; pa.Cl[2] = Vl;
    pa.mode = 1;
    gemm_mma<128, 4><<<dim3(DMOD / 128, M / 128, 3), 256, GSMEM128>>>(pa, DMOD);

    // tensor-core fused attention v5
    cudaFuncSetAttribute(attn_mma,
                         cudaFuncAttributeMaxDynamicSharedMemorySize, ATT_SMEM);
    attn_mma<<<dim3(SS / 128, HH, BB), 256, ATT_SMEM>>>(
        Qh, Ql, Kh, Kl, Vh, Vl, rkt, rvt, x2);

    // output projection (fp32 out), 128x64 tiles -> 256 CTAs
    GemmArgs oa;
    oa.A[0] = x2;  oa.A[1] = x2;  oa.A[2] = x2;
    oa.B[0] = w02; oa.B[1] = w02; oa.B[2] = w02;
    oa.bias[0] = b0; oa.bias[1] = b0; oa.bias[2] = b0;
    oa.C[0] = (float*)d_out; oa.C[1] = (float*)d_out; oa.C[2] = (float*)d_out;
    oa.Ch[0] = oa.Ch[1] = oa.Ch[2] = nullptr;
    oa.Cl[0] = oa.Cl[1] = oa.Cl[2] = nullptr;
    oa.mode = 0;
    gemm_mma<64, 2><<<dim3(DMOD / 64, M / 128, 1), 256, GSMEM64>>>(oa, DMOD);
}

// round 16
// speedup vs baseline: 1.0128x; 1.0128x over previous
#include <cuda_runtime.h>
#include <cuda_bf16.h>
#include <cstdint>

#define BB 2
#define SS 1024
#define DMOD 1024
#define HH 16
#define DH 64
#define NR 21     // 2*MAX_REL+1
#define K2 2048   // 2-plane storage: [hi | lo] per row
// logical GEMM K = 3072 via region remap: A:(hi,lo,hi)  B:(hi,hi,lo)

// ============================================================================
// scratch (static device globals: no allocations allowed)
// ============================================================================
__device__ __nv_bfloat16 g_Qh[BB * SS * DMOD];
__device__ __nv_bfloat16 g_Ql[BB * SS * DMOD];
__device__ __nv_bfloat16 g_Kh[BB * SS * DMOD];
__device__ __nv_bfloat16 g_Kl[BB * SS * DMOD];
__device__ __nv_bfloat16 g_Vh[BB * SS * DMOD];
__device__ __nv_bfloat16 g_Vl[BB * SS * DMOD];

__device__ __nv_bfloat16 g_q2[BB * SS * K2];
__device__ __nv_bfloat16 g_k2[BB * SS * K2];
__device__ __nv_bfloat16 g_v2[BB * SS * K2];
__device__ __nv_bfloat16 g_x2[BB * SS * K2];
__device__ __nv_bfloat16 g_wq2[DMOD * K2];
__device__ __nv_bfloat16 g_wk2[DMOD * K2];
__device__ __nv_bfloat16 g_wv2[DMOD * K2];
__device__ __nv_bfloat16 g_w02[DMOD * K2];

// split-K partial buffers for the out-projection
__device__ float g_P0[BB * SS * DMOD];
__device__ float g_P1[BB * SS * DMOD];

// ============================================================================
// batched split kernel: fp32 -> bf16 [hi | lo]
// ============================================================================
struct SplitPack {
    const float* in[7];
    __nv_bfloat16* out[7];
    int n[7];
};

__global__ __launch_bounds__(256) void split_multi(SplitPack p) {
    const int sl = blockIdx.y;
    const int n = p.n[sl];
    int i = blockIdx.x * blockDim.x + threadIdx.x;
    if (i >= n) return;
    const float* in = p.in[sl];
    __nv_bfloat16* out = p.out[sl];
    int m = i >> 10;          // K = 1024
    int k = i & 1023;
    float x = in[i];
    __nv_bfloat16 h = __float2bfloat16_rn(x);
    float r = x - __bfloat162float(h);
    __nv_bfloat16 l = __float2bfloat16_rn(r);
    size_t base = (size_t)m * K2 + k;
    out[base] = h;
    out[base + 1024] = l;
}

// final combine: out = P0 + P1 + bias  (vectorized)
__global__ __launch_bounds__(256) void combine_kernel(
    const float* __restrict__ P0, const float* __restrict__ P1,
    const float* __restrict__ bias, float* __restrict__ out, int n4) {
    int i = blockIdx.x * blockDim.x + threadIdx.x;
    if (i >= n4) return;
    float4 a = ((const float4*)P0)[i];
    float4 b = ((const float4*)P1)[i];
    const int col4 = i & (DMOD / 4 - 1);
    float4 bv = ((const float4*)bias)[col4];
    ((float4*)out)[i] = make_float4(a.x + b.x + bv.x, a.y + b.y + bv.y,
                                    a.z + b.z + bv.z, a.w + b.w + bv.w);
}

// ============================================================================
// mma.sync / cp.async helpers
// ============================================================================
__device__ __forceinline__ uint32_t smem_u32(const void* p) {
    uint32_t a;
    asm("{ .reg .u64 t; cvta.to.shared.u64 t, %1; cvt.u32.u64 %0, t; }"
        : "=r"(a) : "l"(p));
    return a;
}

#define CP_ASYNC16(dst, src) \
    asm volatile("cp.async.cg.shared.global [%0], [%1], 16;" \
                 :: "r"(dst), "l"(src) : "memory")
#define CP_COMMIT() asm volatile("cp.async.commit_group;" ::: "memory")
#define CP_WAIT0()  asm volatile("cp.async.wait_group 0;" ::: "memory")

__device__ __forceinline__ void ldmx4(uint32_t& r0, uint32_t& r1,
                                      uint32_t& r2, uint32_t& r3,
                                      uint32_t addr) {
    asm volatile(
        "ldmatrix.sync.aligned.m8n8.x4.shared.b16 {%0,%1,%2,%3}, [%4];"
        : "=r"(r0), "=r"(r1), "=r"(r2), "=r"(r3) : "r"(addr));
}

__device__ __forceinline__ void ldmx4t(uint32_t& r0, uint32_t& r1,
                                       uint32_t& r2, uint32_t& r3,
                                       uint32_t addr) {
    asm volatile(
        "ldmatrix.sync.aligned.m8n8.x4.trans.shared.b16 {%0,%1,%2,%3}, [%4];"
        : "=r"(r0), "=r"(r1), "=r"(r2), "=r"(r3) : "r"(addr));
}

__device__ __forceinline__ void mma16816(float* c, const uint32_t* a,
                                         const uint32_t* b) {
    asm volatile(
        "mma.sync.aligned.m16n8k16.row.col.f32.bf16.bf16.f32 "
        "{%0,%1,%2,%3}, {%4,%5,%6,%7}, {%8,%9}, {%0,%1,%2,%3};"
        : "+f"(c[0]), "+f"(c[1]), "+f"(c[2]), "+f"(c[3])
        : "r"(a[0]), "r"(a[1]), "r"(a[2]), "r"(a[3]), "r"(b[0]), "r"(b[1]));
}

__device__ __forceinline__ void split2(float x, __nv_bfloat16& h, __nv_bfloat16& l) {
    h = __float2bfloat16_rn(x);
    l = __float2bfloat16_rn(x - __bfloat162float(h));
}

__device__ __forceinline__ uint32_t pack_bf2(__nv_bfloat16 a, __nv_bfloat16 b) {
    __nv_bfloat162 p = __halves2bfloat162(a, b);
    return *(uint32_t*)&p;
}

// ============================================================================
// bf16 HMMA GEMM, logical K=3072 over 2-plane storage, BK=64, 128x128 tile,
// cp.async single-sync pipeline, 2 CTAs/SM.
//   K-range [kt0*64, (kt0+ntk)*64)  (split-K via grid.z picks kt0)
// mode 0: C fp32 = acc + bias
// mode 1: split bf16 hi/lo planes
// mode 2: C fp32 = acc (raw partial, no bias); C selected by blockIdx.z
// ============================================================================
struct GemmArgs {
    const __nv_bfloat16* A[3];
    const __nv_bfloat16* B[3];
    const float* bias[3];
    float* C[3];
    __nv_bfloat16* Ch[3];
    __nv_bfloat16* Cl[3];
    int mode;
    int ntk;     // pipeline iters per CTA
    int ktz;     // kt0 = blockIdx.z * ktz
};

#define GRS 72                        // halves per smem row (144 B)
#define GBUF (128 * GRS)              // stage halves (A or B)
#define GSMEM (4 * GBUF * 2)          // 73728 B

__global__ __launch_bounds__(256, 2) void gemm_mma(GemmArgs ga, int N) {
    extern __shared__ __align__(16) __nv_bfloat16 gsm[];
    __nv_bfloat16* As = gsm;                  // [2][GBUF]
    __nv_bfloat16* Bs = gsm + 2 * GBUF;       // [2][GBUF]

    const int t = threadIdx.x;
    const int lane = t & 31;
    const int wid = t >> 5;
    const int wm = (wid & 1) * 64;
    const int wn = (wid >> 1) * 32;
    const int grp = lane >> 2;
    const int tig = lane & 3;
    const int z = blockIdx.z;
    const int m0 = blockIdx.y * 128;
    const int n0 = blockIdx.x * 128;
    const int kt0 = z * ga.ktz;

    const __nv_bfloat16* Ag = ga.A[z];
    const __nv_bfloat16* Bg = ga.B[z];

    const int lrow = t >> 1;
    const int lcol = (t & 1) * 32;
    const __nv_bfloat16* Ap = Ag + (size_t)(m0 + lrow) * K2;
    const __nv_bfloat16* Bp = Bg + (size_t)(n0 + lrow) * K2;
    const uint32_t sst = lrow * (GRS * 2) + lcol * 2;

    const uint32_t asb = smem_u32(As);
    const uint32_t bsb = smem_u32(Bs);

    const uint32_t a_base = asb + (wm + (lane & 15)) * (GRS * 2) + ((lane >> 4) * 8) * 2;
    const uint32_t b_base = bsb + (wn + (lane & 7) + ((lane >> 4) & 1) * 8) * (GRS * 2) +
                            (((lane >> 3) & 1) * 8) * 2;

    float acc[4][4][4];
#pragma unroll
    for (int mi = 0; mi < 4; ++mi)
#pragma unroll
        for (int ni = 0; ni < 4; ++ni)
#pragma unroll
            for (int r = 0; r < 4; ++r) acc[mi][ni][r] = 0.f;

    // region remap: A (hi,lo,hi) -> {0,1024,0};  B (hi,hi,lo) -> {0,0,1024}
    auto a_src = [&](int kt) {
        const int g = kt0 + kt;
        const int reg = g >> 4;
        return Ap + (reg == 1 ? 1024 : 0) + (g & 15) * 64 + lcol;
    };
    auto b_src = [&](int kt) {
        const int g = kt0 + kt;
        const int reg = g >> 4;
        return Bp + (reg == 2 ? 1024 : 0) + (g & 15) * 64 + lcol;
    };

    {
        const __nv_bfloat16* a0 = a_src(0);
        const __nv_bfloat16* b0 = b_src(0);
#pragma unroll
        for (int c = 0; c < 4; ++c) {
            CP_ASYNC16(asb + sst + c * 16, a0 + c * 8);
            CP_ASYNC16(bsb + sst + c * 16, b0 + c * 8);
        }
        CP_COMMIT();
    }

    const int NT = ga.ntk;
    for (int kt = 0; kt < NT; ++kt) {
        const int buf = kt & 1;
        CP_WAIT0();
        __syncthreads();

        if (kt + 1 < NT) {
            const uint32_t nb = (buf ^ 1) * (GBUF * 2);
            const __nv_bfloat16* an = a_src(kt + 1);
            const __nv_bfloat16* bn = b_src(kt + 1);
#pragma unroll
            for (int c = 0; c < 4; ++c) {
                CP_ASYNC16(asb + nb + sst + c * 16, an + c * 8);
                CP_ASYNC16(bsb + nb + sst + c * 16, bn + c * 8);
            }
            CP_COMMIT();
        }

        const uint32_t abuf = a_base + buf * (GBUF * 2);
        const uint32_t bbuf = b_base + buf * (GBUF * 2);
#pragma unroll
        for (int ks = 0; ks < 4; ++ks) {
            uint32_t a[4][4], b[4][2];
#pragma unroll
            for (int mi = 0; mi < 4; ++mi)
                ldmx4(a[mi][0], a[mi][1], a[mi][2], a[mi][3],
                      abuf + mi * 16 * (GRS * 2) + ks * 32);
#pragma unroll
            for (int nb2 = 0; nb2 < 2; ++nb2)
                ldmx4(b[nb2 * 2][0], b[nb2 * 2][1], b[nb2 * 2 + 1][0],
                      b[nb2 * 2 + 1][1],
                      bbuf + nb2 * 16 * (GRS * 2) + ks * 32);
#pragma unroll
            for (int mi = 0; mi < 4; ++mi)
#pragma unroll
                for (int ni = 0; ni < 4; ++ni)
                    mma16816(acc[mi][ni], a[mi], b[ni]);
        }
    }

    if (ga.mode == 0) {
        float* C = ga.C[z];
        const float* bias = ga.bias[z];
#pragma unroll
        for (int ni = 0; ni < 4; ++ni) {
            const int col = n0 + wn + ni * 8 + tig * 2;
            const float2 bv = *(const float2*)&bias[col];
#pragma unroll
            for (int mi = 0; mi < 4; ++mi) {
                const int row = m0 + wm + mi * 16 + grp;
                *(float2*)&C[(size_t)row * N + col] =
                    make_float2(acc[mi][ni][0] + bv.x, acc[mi][ni][1] + bv.y);
                *(float2*)&C[(size_t)(row + 8) * N + col] =
                    make_float2(acc[mi][ni][2] + bv.x, acc[mi][ni][3] + bv.y);
            }
        }
    } else if (ga.mode == 2) {
        float* C = ga.C[z];
#pragma unroll
        for (int ni = 0; ni < 4; ++ni) {
            const int col = n0 + wn + ni * 8 + tig * 2;
#pragma unroll
            for (int mi = 0; mi < 4; ++mi) {
                const int row = m0 + wm + mi * 16 + grp;
                *(float2*)&C[(size_t)row * N + col] =
                    make_float2(acc[mi][ni][0], acc[mi][ni][1]);
                *(float2*)&C[(size_t)(row + 8) * N + col] =
                    make_float2(acc[mi][ni][2], acc[mi][ni][3]);
            }
        }
    } else {
        __nv_bfloat16* Ch = ga.Ch[z];
        __nv_bfloat16* Cl = ga.Cl[z];
        const float* bias = ga.bias[z];
#pragma unroll
        for (int ni = 0; ni < 4; ++ni) {
            const int col = n0 + wn + ni * 8 + tig * 2;
            const float2 bv = *(const float2*)&bias[col];
#pragma unroll
            for (int mi = 0; mi < 4; ++mi) {
                const int row = m0 + wm + mi * 16 + grp;
                float f00 = acc[mi][ni][0] + bv.x, f01 = acc[mi][ni][1] + bv.y;
                float f10 = acc[mi][ni][2] + bv.x, f11 = acc[mi][ni][3] + bv.y;
                __nv_bfloat16 h00, l00, h01, l01, h10, l10, h11, l11;
                split2(f00, h00, l00);
                split2(f01, h01, l01);
                split2(f10, h10, l10);
                split2(f11, h11, l11);
                const size_t i0 = (size_t)row * N + col;
                const size_t i1 = (size_t)(row + 8) * N + col;
                *(__nv_bfloat162*)(Ch + i0) = __halves2bfloat162(h00, h01);
                *(__nv_bfloat162*)(Cl + i0) = __halves2bfloat162(l00, l01);
                *(__nv_bfloat162*)(Ch + i1) = __halves2bfloat162(h10, h11);
                *(__nv_bfloat162*)(Cl + i1) = __halves2bfloat162(l10, l11);
            }
        }
    }
}

// ============================================================================
// Tensor-core fused attention v5 (FA2 register-S + clip-band fast path).
// Unchanged from R14.
// ============================================================================
#define QRS 72
#define ATT_SMEM 105984
#define S32 0.03125f

__global__ __launch_bounds__(256, 2) void attn_mma(
    const __nv_bfloat16* __restrict__ Qhg, const __nv_bfloat16* __restrict__ Qlg,
    const __nv_bfloat16* __restrict__ Khg, const __nv_bfloat16* __restrict__ Klg,
    const __nv_bfloat16* __restrict__ Vhg, const __nv_bfloat16* __restrict__ Vlg,
    const float* __restrict__ rkt, const float* __restrict__ rvt,
    __nv_bfloat16* __restrict__ x2) {
    extern __shared__ char smc[];
    __nv_bfloat16* Qh = (__nv_bfloat16*)(smc);
    __nv_bfloat16* Ql = (__nv_bfloat16*)(smc + 18432);
    __nv_bfloat16* Kh = (__nv_bfloat16*)(smc + 36864);
    __nv_bfloat16* Kl = (__nv_bfloat16*)(smc + 46080);
    __nv_bfloat16* Vh = (__nv_bfloat16*)(smc + 55296);
    __nv_bfloat16* Vl = (__nv_bfloat16*)(smc + 64512);
    float* rk = (float*)(smc + 73728);
    float* rv = (float*)(smc + 79104);
    float* pp = (float*)(smc + 84480);
    float* cs = (float*)(smc + 95232);

    const uint32_t sQh = smem_u32(Qh), sQl = smem_u32(Ql);
    const uint32_t sKh = smem_u32(Kh), sKl = smem_u32(Kl);
    const uint32_t sVh = smem_u32(Vh), sVl = smem_u32(Vl);

    const int t = threadIdx.x;
    const int lane = t & 31;
    const int w = t >> 5;
    const int grp = lane >> 2;
    const int tig = lane & 3;
    const int q0 = blockIdx.x * 128;
    const int h = blockIdx.y;
    const int b = blockIdx.z;
    const size_t hoff = (size_t)h * DH;
    const size_t gbase = (size_t)b * SS * DMOD + hoff;

    const int ch = t & 7;
    const int r32 = t >> 3;

    {
        const __nv_bfloat16* qg[2] = {Qhg + gbase, Qlg + gbase};
        __nv_bfloat16* qs[2] = {Qh, Ql};
#pragma unroll
        for (int i = 0; i < 8; ++i) {
            const int pl = i >> 2;
            const int row = r32 + (i & 3) * 32;
            *(uint4*)(qs[pl] + row * QRS + ch * 8) =
                *(const uint4*)(qg[pl] + (size_t)(q0 + row) * DMOD + ch * 8);
        }
    }
    for (int i = t; i < NR * 64; i += 256) { rk[i] = rkt[i]; rv[i] = rvt[i]; }
    for (int i = t; i < 128 * NR; i += 256) cs[i] = 0.f;
    __syncthreads();

    for (int e = t; e < 128 * NR; e += 256) {
        int qq = e / NR, j = e - qq * NR;
        float s = 0.f;
#pragma unroll 16
        for (int d = 0; d < 64; ++d)
            s += (__bfloat162float(Qh[qq * QRS + d]) +
                  __bfloat162float(Ql[qq * QRS + d])) * rk[j * 64 + d];
        pp[e] = s;
    }

    float o[8][4];
#pragma unroll
    for (int ni = 0; ni < 8; ++ni)
#pragma unroll
        for (int r = 0; r < 4; ++r) o[ni][r] = 0.f;

    float l0a[2] = {0.f, 0.f};
    float l20a[2] = {0.f, 0.f};

    const uint32_t a_off = (w * 16 + (lane & 15)) * (QRS * 2) + ((lane >> 4) * 8) * 2;
    const uint32_t b_off = ((lane & 7) + ((lane >> 4) & 1) * 8) * (QRS * 2) +
                           (((lane >> 3) & 1) * 8) * 2;
    const uint32_t vb_row = (lane & 7) + ((lane >> 3) & 1) * 8;
    const uint32_t vb_cb  = ((lane >> 4) * 8) * 2;

    const __nv_bfloat16* kvg[4] = {Khg + gbase, Klg + gbase, Vhg + gbase, Vlg + gbase};
    __nv_bfloat16* kvs[4] = {Kh, Kl, Vh, Vl};

    for (int kt = 0; kt < 16; ++kt) {
        const int k0 = kt * 64;
        __syncthreads();

#pragma unroll
        for (int i = 0; i < 8; ++i) {
            const int pl = i >> 1;
            const int row = r32 + (i & 1) * 32;
            *(uint4*)(kvs[pl] + row * QRS + ch * 8) =
                *(const uint4*)(kvg[pl] + (size_t)(k0 + row) * DMOD + ch * 8);
        }
        __syncthreads();

        float s[8][4];
#pragma unroll
        for (int ni = 0; ni < 8; ++ni)
#pragma unroll
            for (int r = 0; r < 4; ++r) s[ni][r] = 0.f;

#pragma unroll
        for (int ks = 0; ks < 4; ++ks) {
            uint32_t ah[4], al[4];
            ldmx4(ah[0], ah[1], ah[2], ah[3], sQh + a_off + ks * 32);
            ldmx4(al[0], al[1], al[2], al[3], sQl + a_off + ks * 32);
#pragma unroll
            for (int nb = 0; nb < 4; ++nb) {
                uint32_t kh[4], kl[4];
                ldmx4(kh[0], kh[1], kh[2], kh[3],
                      sKh + b_off + nb * 16 * (QRS * 2) + ks * 32);
                ldmx4(kl[0], kl[1], kl[2], kl[3],
                      sKl + b_off + nb * 16 * (QRS * 2) + ks * 32);
                uint32_t bh0[2] = {kh[0], kh[1]}, bh1[2] = {kh[2], kh[3]};
                uint32_t bl0[2] = {kl[0], kl[1]}, bl1[2] = {kl[2], kl[3]};
                mma16816(s[nb * 2],     ah, bh0);
                mma16816(s[nb * 2],     al, bh0);
                mma16816(s[nb * 2],     ah, bl0);
                mma16816(s[nb * 2 + 1], ah, bh1);
                mma16816(s[nb * 2 + 1], al, bh1);
                mma16816(s[nb * 2 + 1], ah, bl1);
            }
        }

        uint32_t ahf[4][4], alf[4][4];
        const int wq0 = q0 + w * 16;
        const int dmax = k0 + 63 - wq0;
        const int dmin = k0 - (wq0 + 15);

        if (dmax <= -10 || dmin >= 10) {
            const int cls = (dmax <= -10) ? 0 : 20;
            float* lacc = (dmax <= -10) ? l0a : l20a;
#pragma unroll
            for (int hf = 0; hf < 2; ++hf) {
                const int row = w * 16 + grp + hf * 8;
                const float ppc = pp[row * NR + cls];
                float acc = 0.f;
#pragma unroll
                for (int ni = 0; ni < 8; ++ni) {
                    const float f0 = (s[ni][hf * 2 + 0] + ppc) * S32;
                    const float f1 = (s[ni][hf * 2 + 1] + ppc) * S32;
                    acc += f0;
                    acc += f1;
                    __nv_bfloat16 h0, lo0, h1, lo1;
                    split2(f0, h0, lo0);
                    split2(f1, h1, lo1);
                    const int kc = ni >> 1;
                    const int sub = (ni & 1) * 2 + hf;
                    ahf[kc][sub] = pack_bf2(h0, h1);
                    alf[kc][sub] = pack_bf2(lo0, lo1);
                }
                lacc[hf] += acc;
            }
        } else {
#pragma unroll
            for (int ni = 0; ni < 8; ++ni) {
                const int colg = k0 + ni * 8 + tig * 2;
#pragma unroll
                for (int hf = 0; hf < 2; ++hf) {
                    const int row = w * 16 + grp + hf * 8;
                    const int gq = q0 + row;
                    const float* ppr = pp + row * NR;
                    const int d0 = colg - gq;
                    const int d1 = d0 + 1;
                    const int c0 = d0 < -10 ? 0 : (d0 > 10 ? 20 : d0 + 10);
                    const int c1 = d1 < -10 ? 0 : (d1 > 10 ? 20 : d1 + 10);
                    const float f0 = (s[ni][hf * 2 + 0] + ppr[c0]) * S32;
                    const float f1 = (s[ni][hf * 2 + 1] + ppr[c1]) * S32;
                    if (d0 <= -10)      l0a[hf]  += f0;
                    else if (d0 >= 10)  l20a[hf] += f0;
                    else                cs[row * NR + d0 + 10] += f0;
                    if (d1 <= -10)      l0a[hf]  += f1;
                    else if (d1 >= 10)  l20a[hf] += f1;
                    else                cs[row * NR + d1 + 10] += f1;
                    __nv_bfloat16 h0, lo0, h1, lo1;
                    split2(f0, h0, lo0);
                    split2(f1, h1, lo1);
                    const int kc = ni >> 1;
                    const int sub = (ni & 1) * 2 + hf;
                    ahf[kc][sub] = pack_bf2(h0, h1);
                    alf[kc][sub] = pack_bf2(lo0, lo1);
                }
            }
        }

#pragma unroll
        for (int kc = 0; kc < 4; ++kc) {
#pragma unroll
            for (int nb = 0; nb < 4; ++nb) {
                uint32_t vh[4], vl[4];
                ldmx4t(vh[0], vh[1], vh[2], vh[3],
                       sVh + (kc * 16 + vb_row) * (QRS * 2) + vb_cb + nb * 32);
                ldmx4t(vl[0], vl[1], vl[2], vl[3],
                       sVl + (kc * 16 + vb_row) * (QRS * 2) + vb_cb + nb * 32);
                uint32_t bh0[2] = {vh[0], vh[1]}, bh1[2] = {vh[2], vh[3]};
                uint32_t bl0[2] = {vl[0], vl[1]}, bl1[2] = {vl[2], vl[3]};
                mma16816(o[nb * 2],     ahf[kc], bh0);
                mma16816(o[nb * 2],     alf[kc], bh0);
                mma16816(o[nb * 2],     ahf[kc], bl0);
                mma16816(o[nb * 2 + 1], ahf[kc], bh1);
                mma16816(o[nb * 2 + 1], alf[kc], bh1);
                mma16816(o[nb * 2 + 1], ahf[kc], bl1);
            }
        }
    }

#pragma unroll
    for (int hf = 0; hf < 2; ++hf) {
        float v0 = l0a[hf];
        v0 += __shfl_xor_sync(0xffffffffu, v0, 1);
        v0 += __shfl_xor_sync(0xffffffffu, v0, 2);
        float v20 = l20a[hf];
        v20 += __shfl_xor_sync(0xffffffffu, v20, 1);
        v20 += __shfl_xor_sync(0xffffffffu, v20, 2);
        if (tig == 0) {
            const int row = w * 16 + grp + hf * 8;
            cs[row * NR + 0]  += v0;
            cs[row * NR + 20] += v20;
        }
    }
    __syncwarp();

#pragma unroll
    for (int ni = 0; ni < 8; ++ni) {
#pragma unroll
        for (int hf = 0; hf < 2; ++hf) {
            const int row = w * 16 + grp + hf * 8;
            const int col = ni * 8 + tig * 2;
            float a0 = o[ni][hf * 2 + 0];
            float a1 = o[ni][hf * 2 + 1];
            const float* csr = cs + row * NR;
#pragma unroll
            for (int j = 0; j < NR; ++j) {
                const float c = csr[j];
                a0 += c * rv[j * 64 + col];
                a1 += c * rv[j * 64 + col + 1];
            }
            __nv_bfloat16 h0, l0b, h1, l1b;
            split2(a0, h0, l0b);
            split2(a1, h1, l1b);
            const size_t base = ((size_t)b * SS + q0 + row) * K2 + hoff + col;
            *(__nv_bfloat162*)(x2 + base)        = __halves2bfloat162(h0, h1);
            *(__nv_bfloat162*)(x2 + base + 1024) = __halves2bfloat162(l0b, l1b);
        }
    }
}

// ============================================================================
// launch
// ============================================================================
extern "C" void kernel_launch(void* const* d_in, const int* in_sizes, int n_in,
                              void* d_out, int out_size) {
    const float* q   = (const float*)d_in[0];
    const float* k   = (const float*)d_in[1];
    const float* v   = (const float*)d_in[2];
    const float* Wq  = (const float*)d_in[4];
    const float* bq  = (const float*)d_in[5];
    const float* Wk  = (const float*)d_in[6];
    const float* bk  = (const float*)d_in[7];
    const float* Wv  = (const float*)d_in[8];
    const float* bv  = (const float*)d_in[9];
    const float* W0  = (const float*)d_in[10];
    const float* b0  = (const float*)d_in[11];
    const float* rkt = (const float*)d_in[12];
    const float* rvt = (const float*)d_in[13];

    __nv_bfloat16 *Qh, *Ql, *Kh, *Kl, *Vh, *Vl;
    cudaGetSymbolAddress((void**)&Qh, g_Qh);
    cudaGetSymbolAddress((void**)&Ql, g_Ql);
    cudaGetSymbolAddress((void**)&Kh, g_Kh);
    cudaGetSymbolAddress((void**)&Kl, g_Kl);
    cudaGetSymbolAddress((void**)&Vh, g_Vh);
    cudaGetSymbolAddress((void**)&Vl, g_Vl);
    __nv_bfloat16 *q2, *k2, *v2, *x2, *wq2, *wk2, *wv2, *w02;
    cudaGetSymbolAddress((void**)&q2, g_q2);
    cudaGetSymbolAddress((void**)&k2, g_k2);
    cudaGetSymbolAddress((void**)&v2, g_v2);
    cudaGetSymbolAddress((void**)&x2, g_x2);
    cudaGetSymbolAddress((void**)&wq2, g_wq2);
    cudaGetSymbolAddress((void**)&wk2, g_wk2);
    cudaGetSymbolAddress((void**)&wv2, g_wv2);
    cudaGetSymbolAddress((void**)&w02, g_w02);
    float *P0, *P1;
    cudaGetSymbolAddress((void**)&P0, g_P0);
    cudaGetSymbolAddress((void**)&P1, g_P1);

    const int M = BB * SS;          // 2048
    const int NACT = M * DMOD;      // 2M
    const int NW = DMOD * DMOD;     // 1M

    // one batched split launch for all 7 tensors
    SplitPack sp;
    sp.in[0] = q;  sp.out[0] = q2;  sp.n[0] = NACT;
    sp.in[1] = k;  sp.out[1] = k2;  sp.n[1] = NACT;
    sp.in[2] = v;  sp.out[2] = v2;  sp.n[2] = NACT;
    sp.in[3] = Wq; sp.out[3] = wq2; sp.n[3] = NW;
    sp.in[4] = Wk; sp.out[4] = wk2; sp.n[4] = NW;
    sp.in[5] = Wv; sp.out[5] = wv2; sp.n[5] = NW;
    sp.in[6] = W0; sp.out[6] = w02; sp.n[6] = NW;
    split_multi<<<dim3(NACT / 256, 7), 256>>>(sp);

    cudaFuncSetAttribute(gemm_mma,
                         cudaFuncAttributeMaxDynamicSharedMemorySize, GSMEM);

    // fused q/k/v projections -> pre-split bf16 hi/lo planes (full K, z = gemm id)
    GemmArgs pa;
    pa.A[0] = q2;  pa.A[1] = k2;  pa.A[2] = v2;
    pa.B[0] = wq2; pa.B[1] = wk2; pa.B[2] = wv2;
    pa.bias[0] = bq; pa.bias[1] = bk; pa.bias[2] = bv;
    pa.C[0] = pa.C[1] = pa.C[2] = nullptr;
    pa.Ch[0] = Qh; pa.Ch[1] = Kh; pa.Ch[2] = Vh;
    pa.Cl[0] = Ql; pa.Cl[1] = Kl; pa.Cl[2] = Vl;
    pa.mode = 1;
    pa.ntk = 48;
    pa.ktz = 0;
    gemm_mma<<<dim3(DMOD / 128, M / 128, 3), 256, GSMEM>>>(pa, DMOD);

    // tensor-core fused attention v5
    cudaFuncSetAttribute(attn_mma,
                         cudaFuncAttributeMaxDynamicSharedMemorySize, ATT_SMEM);
    attn_mma<<<dim3(SS / 128, HH, BB), 256, ATT_SMEM>>>(
        Qh, Ql, Kh, Kl, Vh, Vl, rkt, rvt, x2);

    // output projection: split-K=2 (z = K-half), partials then combine
    GemmArgs oa;
    oa.A[0] = x2;  oa.A[1] = x2;  oa.A[2] = x2;
    oa.B[0] = w02; oa.B[1] = w02; oa.B[2] = w02;
    oa.bias[0] = b0; oa.bias[1] = b0; oa.bias[2] = b0;
    oa.C[0] = P0; oa.C[1] = P1; oa.C[2] = nullptr;
    oa.Ch[0] = oa.Ch[1] = oa.Ch[2] = nullptr;
    oa.Cl[0] = oa.Cl[1] = oa.Cl[2] = nullptr;
    oa.mode = 2;
    oa.ntk = 24;
    oa.ktz = 24;
    gemm_mma<<<dim3(DMOD / 128, M / 128, 2), 256, GSMEM>>>(oa, DMOD);

    combine_kernel<<<(NACT / 4 + 255) / 256, 256>>>(
        P0, P1, b0, (float*)d_out, NACT / 4);
}